// round 3
// baseline (speedup 1.0000x reference)
#include <cuda_runtime.h>
#include <cuda_bf16.h>

// GCN(2-layer, linear) + linear head collapses algebraically:
//   w  = W1 @ W2 @ Wc  (R^256)          t[i]  = x[i]·w
//   s2 = Agg(t) + t*dinv^2 + c1         out   = Agg(s2) + s2*dinv^2 + c2
// Agg(h)[d] = sum_e dinv[src]*ew*dinv[d]*h[src];  dinv = rsqrt(deg+1).
// edge_index arrives int32 (JAX x64 disabled downgrades int64 silently).
// g_deg protocol: zero at entry of every launch; k_dinv consumes it (+1 for
// self-loop) and re-zeroes it for the next graph replay.

#define NN 50000
#define IND 256
#define HID 128

__device__ float g_deg[NN];    // zero-init at load; re-zeroed by k_dinv
__device__ float g_dinv[NN];
__device__ float g_t[NN];
__device__ float g_s2[NN];
__device__ float g_w[IND];
__device__ float g_c[2];       // c1, c2

// K1: collapse weights. One block, 256 threads.
__global__ void k_prep(const float* __restrict__ W1, const float* __restrict__ b1,
                       const float* __restrict__ W2, const float* __restrict__ b2,
                       const float* __restrict__ Wc, const float* __restrict__ bc) {
    __shared__ float v[HID];
    int tid = threadIdx.x;
    if (tid < HID) {
        double a = 0.0;
        for (int j = 0; j < HID; j++) a += (double)W2[tid * HID + j] * (double)Wc[j];
        v[tid] = (float)a;
    }
    __syncthreads();
    {
        double a = 0.0;
        for (int k = 0; k < HID; k++) a += (double)W1[tid * HID + k] * (double)v[k];
        g_w[tid] = (float)a;
    }
    if (tid == 0) {
        double a1 = 0.0, a2 = 0.0;
        for (int k = 0; k < HID; k++) { a1 += (double)b1[k] * (double)v[k];
                                        a2 += (double)b2[k] * (double)Wc[k]; }
        g_c[0] = (float)a1;
        g_c[1] = (float)(a2 + (double)bc[0]);
    }
}

// K2 (fused, race-free): blocks [0, tblocks) do warp-per-node dot t[i]=x[i]·w;
// blocks [tblocks, ...) scatter edge weights into the ZERO g_deg buffer.
// The two halves touch disjoint arrays.
__global__ void k_t_deg(const float* __restrict__ x,
                        const int* __restrict__ dst,
                        const float* __restrict__ ew,
                        int n, int e, int tblocks) {
    if (blockIdx.x < tblocks) {
        int gtid = blockIdx.x * blockDim.x + threadIdx.x;
        int node = gtid >> 5;
        int lane = gtid & 31;
        if (node >= n) return;
        const float4* xr = (const float4*)(x + (size_t)node * IND);
        float4 p = __ldg(&xr[lane]);
        float4 q = __ldg(&xr[lane + 32]);
        int b0 = 4 * lane, b1i = 4 * (lane + 32);
        float a = p.x * g_w[b0]      + p.y * g_w[b0 + 1]
                + p.z * g_w[b0 + 2]  + p.w * g_w[b0 + 3]
                + q.x * g_w[b1i]     + q.y * g_w[b1i + 1]
                + q.z * g_w[b1i + 2] + q.w * g_w[b1i + 3];
        #pragma unroll
        for (int off = 16; off > 0; off >>= 1)
            a += __shfl_down_sync(0xFFFFFFFFu, a, off);
        if (lane == 0) g_t[node] = a;
    } else {
        int i = (blockIdx.x - tblocks) * blockDim.x + threadIdx.x;
        if (i >= e) return;
        atomicAdd(&g_deg[dst[i]], ew[i]);
    }
}

// K3: dinv = rsqrt(deg+1); init s2 with self-loop + c1; re-zero g_deg.
__global__ void k_dinv(int n) {
    int i = blockIdx.x * blockDim.x + threadIdx.x;
    if (i >= n) return;
    float di = rsqrtf(g_deg[i] + 1.0f);
    g_deg[i] = 0.0f;                       // ready for next graph replay
    g_dinv[i] = di;
    g_s2[i] = g_t[i] * di * di + g_c[0];
}

// K4: layer-1 scalar propagation
__global__ void k_prop1(const int* __restrict__ src,
                        const int* __restrict__ dst,
                        const float* __restrict__ ew, int e) {
    int i = blockIdx.x * blockDim.x + threadIdx.x;
    if (i >= e) return;
    int s = src[i], d = dst[i];
    float nm = g_dinv[s] * ew[i] * g_dinv[d];
    atomicAdd(&g_s2[d], g_t[s] * nm);
}

// K5: init out with layer-2 self-loop + c2
__global__ void k_out_init(float* __restrict__ out, int n) {
    int i = blockIdx.x * blockDim.x + threadIdx.x;
    if (i >= n) return;
    float di = g_dinv[i];
    out[i] = g_s2[i] * di * di + g_c[1];
}

// K6: layer-2 scalar propagation (norm recomputed; dinv is L2-resident)
__global__ void k_prop2(float* __restrict__ out,
                        const int* __restrict__ src,
                        const int* __restrict__ dst,
                        const float* __restrict__ ew, int e) {
    int i = blockIdx.x * blockDim.x + threadIdx.x;
    if (i >= e) return;
    int s = src[i], d = dst[i];
    float nm = g_dinv[s] * ew[i] * g_dinv[d];
    atomicAdd(&out[d], g_s2[s] * nm);
}

extern "C" void kernel_launch(void* const* d_in, const int* in_sizes, int n_in,
                              void* d_out, int out_size) {
    const float* x  = (const float*)d_in[0];
    const int*   ei = (const int*)d_in[1];    // [2, E] int32
    const float* ew = (const float*)d_in[2];
    const float* W1 = (const float*)d_in[3];
    const float* b1 = (const float*)d_in[4];
    const float* W2 = (const float*)d_in[5];
    const float* b2 = (const float*)d_in[6];
    const float* Wc = (const float*)d_in[7];
    const float* bc = (const float*)d_in[8];
    float* out = (float*)d_out;

    const int E = in_sizes[2];
    const int N = in_sizes[0] / IND;
    const int* src = ei;
    const int* dst = ei + E;

    k_prep<<<1, 256>>>(W1, b1, W2, b2, Wc, bc);

    int tblocks = (N * 32 + 255) / 256;   // warp-per-node
    int eblocks = (E + 255) / 256;
    int nblocks = (N + 255) / 256;

    k_t_deg<<<tblocks + eblocks, 256>>>(x, dst, ew, N, E, tblocks);
    k_dinv<<<nblocks, 256>>>(N);
    k_prop1<<<eblocks, 256>>>(src, dst, ew, E);
    k_out_init<<<nblocks, 256>>>(out, N);
    k_prop2<<<eblocks, 256>>>(out, src, dst, ew, E);
}

// round 5
// speedup vs baseline: 1.0488x; 1.0488x over previous
#include <cuda_runtime.h>
#include <cuda_bf16.h>

// Collapsed 2-layer linear GCN + linear head:
//   w = W1@W2@Wc (R^256);  t[i] = x[i]·w
//   Agg(h)[d] = dinv[d] * sum_e (h[s]*dinv[s]) * ew    <- dinv[d] factored OUT
//   u = t*dinv;  s2 = dinv*(acc1 + u) + c1   (acc1[d] = sum u[s]*ew)
//   v = s2*dinv; out = dinv*(acc2 + v) + c2  (acc2[d] = sum v[s]*ew)
// Edge pass = ONE random gather (u[s] or v[s], L2-resident 200KB) + ONE atomic.
// Replay protocol: g_deg zeroed by k_dinv; g_acc zeroed by k_mid and k_final.
// NOTE: __device__ symbols are NEVER passed as kernel args from host (host
// shadow address != device address); selection happens in device code.

#define NN 50000
#define IND 256
#define HID 128

__device__ float g_deg[NN];    // zero-init at load; re-zeroed by k_dinv
__device__ float g_acc[NN];    // zero-init; zeroed by k_mid / k_final
__device__ float g_dinv[NN];
__device__ float g_t[NN];
__device__ float g_u[NN];      // t*dinv   (layer-1 edge operand)
__device__ float g_v[NN];      // s2*dinv  (layer-2 edge operand)
__device__ float g_w[IND];
__device__ float g_c[2];       // c1, c2

// K1: collapse weights (one block, 256 threads).
__global__ void k_prep(const float* __restrict__ W1, const float* __restrict__ b1,
                       const float* __restrict__ W2, const float* __restrict__ b2,
                       const float* __restrict__ Wc, const float* __restrict__ bc) {
    __shared__ float v[HID];
    int tid = threadIdx.x;
    if (tid < HID) {
        double a = 0.0;
        for (int j = 0; j < HID; j++) a += (double)W2[tid * HID + j] * (double)Wc[j];
        v[tid] = (float)a;
    }
    __syncthreads();
    {
        double a = 0.0;
        for (int k = 0; k < HID; k++) a += (double)W1[tid * HID + k] * (double)v[k];
        g_w[tid] = (float)a;
    }
    if (tid == 0) {
        double a1 = 0.0, a2 = 0.0;
        for (int k = 0; k < HID; k++) { a1 += (double)b1[k] * (double)v[k];
                                        a2 += (double)b2[k] * (double)Wc[k]; }
        g_c[0] = (float)a1;
        g_c[1] = (float)(a2 + (double)bc[0]);
    }
}

// K2 (fused, race-free disjoint outputs): node blocks compute t[i]=x[i]·w
// (warp-per-node); edge blocks scatter ew into zeroed g_deg, 4 edges/thread.
__global__ void k_t_deg(const float* __restrict__ x,
                        const int* __restrict__ dst,
                        const float* __restrict__ ew,
                        int n, int e, int tblocks) {
    if (blockIdx.x < tblocks) {
        int gtid = blockIdx.x * blockDim.x + threadIdx.x;
        int node = gtid >> 5;
        int lane = gtid & 31;
        if (node >= n) return;
        const float4* xr = (const float4*)(x + (size_t)node * IND);
        float4 p = __ldg(&xr[lane]);
        float4 q = __ldg(&xr[lane + 32]);
        int b0 = 4 * lane, b1i = 4 * (lane + 32);
        float a = p.x * g_w[b0]      + p.y * g_w[b0 + 1]
                + p.z * g_w[b0 + 2]  + p.w * g_w[b0 + 3]
                + q.x * g_w[b1i]     + q.y * g_w[b1i + 1]
                + q.z * g_w[b1i + 2] + q.w * g_w[b1i + 3];
        #pragma unroll
        for (int off = 16; off > 0; off >>= 1)
            a += __shfl_down_sync(0xFFFFFFFFu, a, off);
        if (lane == 0) g_t[node] = a;
    } else {
        int i = (blockIdx.x - tblocks) * blockDim.x + threadIdx.x;
        int e4 = e >> 2;
        if (i < e4) {
            int4   d = ((const int4*)dst)[i];
            float4 w = ((const float4*)ew)[i];
            atomicAdd(&g_deg[d.x], w.x);
            atomicAdd(&g_deg[d.y], w.y);
            atomicAdd(&g_deg[d.z], w.z);
            atomicAdd(&g_deg[d.w], w.w);
        } else if (i == e4) {           // scalar tail (e % 4)
            for (int j = e & ~3; j < e; j++) atomicAdd(&g_deg[dst[j]], ew[j]);
        }
    }
}

// K3: dinv = rsqrt(deg+1); u = t*dinv; re-zero g_deg for next replay.
__global__ void k_dinv(int n) {
    int i = blockIdx.x * blockDim.x + threadIdx.x;
    if (i >= n) return;
    float di = rsqrtf(g_deg[i] + 1.0f);
    g_deg[i] = 0.0f;
    g_dinv[i] = di;
    g_u[i] = g_t[i] * di;
}

// K4/K6: edge scatter acc[d] += op[s]*ew, 4 edges/thread, 1 gather + 1 atomic.
// 'which' selects the operand array IN DEVICE CODE (0 -> g_u, 1 -> g_v).
__global__ void k_prop(const int* __restrict__ src,
                       const int* __restrict__ dst,
                       const float* __restrict__ ew,
                       int which, int e) {
    const float* __restrict__ op = which ? g_v : g_u;
    int i = blockIdx.x * blockDim.x + threadIdx.x;
    int e4 = e >> 2;
    if (i < e4) {
        int4   s = ((const int4*)src)[i];
        int4   d = ((const int4*)dst)[i];
        float4 w = ((const float4*)ew)[i];
        float ax = op[s.x], ay = op[s.y], az = op[s.z], aw = op[s.w];
        atomicAdd(&g_acc[d.x], ax * w.x);
        atomicAdd(&g_acc[d.y], ay * w.y);
        atomicAdd(&g_acc[d.z], az * w.z);
        atomicAdd(&g_acc[d.w], aw * w.w);
    } else if (i == e4) {
        for (int j = e & ~3; j < e; j++)
            atomicAdd(&g_acc[dst[j]], op[src[j]] * ew[j]);
    }
}

// K5: s2 = dinv*(acc+u)+c1 ; v = s2*dinv ; zero acc for layer 2.
__global__ void k_mid(int n) {
    int i = blockIdx.x * blockDim.x + threadIdx.x;
    if (i >= n) return;
    float di = g_dinv[i];
    float s2 = di * (g_acc[i] + g_u[i]) + g_c[0];
    g_acc[i] = 0.0f;
    g_v[i] = s2 * di;
}

// K7: out = dinv*(acc+v)+c2 ; zero acc for next replay.
__global__ void k_final(float* __restrict__ out, int n) {
    int i = blockIdx.x * blockDim.x + threadIdx.x;
    if (i >= n) return;
    float di = g_dinv[i];
    out[i] = di * (g_acc[i] + g_v[i]) + g_c[1];
    g_acc[i] = 0.0f;
}

extern "C" void kernel_launch(void* const* d_in, const int* in_sizes, int n_in,
                              void* d_out, int out_size) {
    const float* x  = (const float*)d_in[0];
    const int*   ei = (const int*)d_in[1];    // [2, E] int32
    const float* ew = (const float*)d_in[2];
    const float* W1 = (const float*)d_in[3];
    const float* b1 = (const float*)d_in[4];
    const float* W2 = (const float*)d_in[5];
    const float* b2 = (const float*)d_in[6];
    const float* Wc = (const float*)d_in[7];
    const float* bc = (const float*)d_in[8];
    float* out = (float*)d_out;

    const int E = in_sizes[2];
    const int N = in_sizes[0] / IND;
    const int* src = ei;
    const int* dst = ei + E;

    k_prep<<<1, 256>>>(W1, b1, W2, b2, Wc, bc);

    int tblocks  = (N * 32 + 255) / 256;            // warp-per-node
    int eblocks4 = (E / 4 + 1 + 255) / 256;         // 4 edges/thread (+tail slot)
    int nblocks  = (N + 255) / 256;

    k_t_deg<<<tblocks + eblocks4, 256>>>(x, dst, ew, N, E, tblocks);
    k_dinv<<<nblocks, 256>>>(N);
    k_prop<<<eblocks4, 256>>>(src, dst, ew, 0, E);
    k_mid<<<nblocks, 256>>>(N);
    k_prop<<<eblocks4, 256>>>(src, dst, ew, 1, E);
    k_final<<<nblocks, 256>>>(out, N);
}

// round 6
// speedup vs baseline: 1.0773x; 1.0272x over previous
#include <cuda_runtime.h>
#include <cuda_bf16.h>

// Collapsed 2-layer linear GCN + linear head:
//   w = W1@W2@Wc (R^256);  t[i] = x[i]·w
//   Agg(h)[d] = dinv[d] * sum_e (h[s]*dinv[s]) * ew
//   u = t*dinv;  s2 = dinv*(acc1 + u) + c1
//   v = s2*dinv; out = dinv*(acc2 + v) + c2
// Edge pass = ONE random gather (L2-resident 200KB) + ONE atomic (REDG).
// 2 edges/thread: 400k threads -> full 2048 thr/SM for latency hiding.
// Replay protocol: g_deg zeroed by k_dinv; g_acc zeroed by k_mid/k_final.
// __device__ symbols never passed as kernel args from host.

#define NN 50000
#define IND 256
#define HID 128

__device__ float g_deg[NN];    // zero-init at load; re-zeroed by k_dinv
__device__ float g_acc[NN];    // zero-init; zeroed by k_mid / k_final
__device__ float g_dinv[NN];
__device__ float g_t[NN];
__device__ float g_u[NN];      // t*dinv   (layer-1 edge operand)
__device__ float g_v[NN];      // s2*dinv  (layer-2 edge operand)
__device__ float g_w[IND];
__device__ float g_c[2];       // c1, c2

// K1: collapse weights (one block, 256 threads).
__global__ void k_prep(const float* __restrict__ W1, const float* __restrict__ b1,
                       const float* __restrict__ W2, const float* __restrict__ b2,
                       const float* __restrict__ Wc, const float* __restrict__ bc) {
    __shared__ float v[HID];
    int tid = threadIdx.x;
    if (tid < HID) {
        double a = 0.0;
        for (int j = 0; j < HID; j++) a += (double)W2[tid * HID + j] * (double)Wc[j];
        v[tid] = (float)a;
    }
    __syncthreads();
    {
        double a = 0.0;
        for (int k = 0; k < HID; k++) a += (double)W1[tid * HID + k] * (double)v[k];
        g_w[tid] = (float)a;
    }
    if (tid == 0) {
        double a1 = 0.0, a2 = 0.0;
        for (int k = 0; k < HID; k++) { a1 += (double)b1[k] * (double)v[k];
                                        a2 += (double)b2[k] * (double)Wc[k]; }
        g_c[0] = (float)a1;
        g_c[1] = (float)(a2 + (double)bc[0]);
    }
}

// K2 (fused, disjoint outputs): node blocks compute t[i]=x[i]·w (warp-per-node,
// 8 nodes/block); edge blocks scatter ew into zeroed g_deg, 2 edges/thread.
__global__ void k_t_deg(const float* __restrict__ x,
                        const int* __restrict__ dst,
                        const float* __restrict__ ew,
                        int n, int e, int tblocks) {
    if (blockIdx.x < tblocks) {
        int gtid = blockIdx.x * blockDim.x + threadIdx.x;
        int node = gtid >> 5;
        int lane = gtid & 31;
        if (node >= n) return;
        const float4* xr = (const float4*)(x + (size_t)node * IND);
        float4 p = __ldg(&xr[lane]);
        float4 q = __ldg(&xr[lane + 32]);
        int b0 = 4 * lane, b1i = 4 * (lane + 32);
        float a = p.x * g_w[b0]      + p.y * g_w[b0 + 1]
                + p.z * g_w[b0 + 2]  + p.w * g_w[b0 + 3]
                + q.x * g_w[b1i]     + q.y * g_w[b1i + 1]
                + q.z * g_w[b1i + 2] + q.w * g_w[b1i + 3];
        #pragma unroll
        for (int off = 16; off > 0; off >>= 1)
            a += __shfl_down_sync(0xFFFFFFFFu, a, off);
        if (lane == 0) g_t[node] = a;
    } else {
        int i = (blockIdx.x - tblocks) * blockDim.x + threadIdx.x;
        int e2 = e >> 1;
        if (i < e2) {
            int2   d = ((const int2*)dst)[i];
            float2 w = ((const float2*)ew)[i];
            atomicAdd(&g_deg[d.x], w.x);
            atomicAdd(&g_deg[d.y], w.y);
        } else if (i == e2 && (e & 1)) {
            atomicAdd(&g_deg[dst[e - 1]], ew[e - 1]);
        }
    }
}

// K3: dinv = rsqrt(deg+1); u = t*dinv; re-zero g_deg. float4 over N/4.
__global__ void k_dinv(int n4) {
    int i = blockIdx.x * blockDim.x + threadIdx.x;
    if (i >= n4) return;
    float4 dg = ((const float4*)g_deg)[i];
    float4 tt = ((const float4*)g_t)[i];
    float4 di;
    di.x = rsqrtf(dg.x + 1.0f);  di.y = rsqrtf(dg.y + 1.0f);
    di.z = rsqrtf(dg.z + 1.0f);  di.w = rsqrtf(dg.w + 1.0f);
    ((float4*)g_deg)[i] = make_float4(0.f, 0.f, 0.f, 0.f);
    ((float4*)g_dinv)[i] = di;
    ((float4*)g_u)[i] = make_float4(tt.x * di.x, tt.y * di.y,
                                    tt.z * di.z, tt.w * di.w);
}

// K4/K6: acc[d] += op[s]*ew, 2 edges/thread; which: 0 -> g_u, 1 -> g_v.
__global__ void k_prop(const int* __restrict__ src,
                       const int* __restrict__ dst,
                       const float* __restrict__ ew,
                       int which, int e) {
    const float* __restrict__ op = which ? g_v : g_u;
    int i = blockIdx.x * blockDim.x + threadIdx.x;
    int e2 = e >> 1;
    if (i < e2) {
        int2   s = ((const int2*)src)[i];
        int2   d = ((const int2*)dst)[i];
        float2 w = ((const float2*)ew)[i];
        float ax = op[s.x], ay = op[s.y];
        atomicAdd(&g_acc[d.x], ax * w.x);
        atomicAdd(&g_acc[d.y], ay * w.y);
    } else if (i == e2 && (e & 1)) {
        atomicAdd(&g_acc[dst[e - 1]], op[src[e - 1]] * ew[e - 1]);
    }
}

// K5: s2 = dinv*(acc+u)+c1 ; v = s2*dinv ; zero acc. float4 over N/4.
__global__ void k_mid(int n4) {
    int i = blockIdx.x * blockDim.x + threadIdx.x;
    if (i >= n4) return;
    float4 di = ((const float4*)g_dinv)[i];
    float4 ac = ((const float4*)g_acc)[i];
    float4 uu = ((const float4*)g_u)[i];
    float c1 = g_c[0];
    float4 vv;
    vv.x = (di.x * (ac.x + uu.x) + c1) * di.x;
    vv.y = (di.y * (ac.y + uu.y) + c1) * di.y;
    vv.z = (di.z * (ac.z + uu.z) + c1) * di.z;
    vv.w = (di.w * (ac.w + uu.w) + c1) * di.w;
    ((float4*)g_acc)[i] = make_float4(0.f, 0.f, 0.f, 0.f);
    ((float4*)g_v)[i] = vv;
}

// K7: out = dinv*(acc+v)+c2 ; zero acc. float4 over N/4.
__global__ void k_final(float* __restrict__ out, int n4) {
    int i = blockIdx.x * blockDim.x + threadIdx.x;
    if (i >= n4) return;
    float4 di = ((const float4*)g_dinv)[i];
    float4 ac = ((const float4*)g_acc)[i];
    float4 vv = ((const float4*)g_v)[i];
    float c2 = g_c[1];
    float4 o;
    o.x = di.x * (ac.x + vv.x) + c2;
    o.y = di.y * (ac.y + vv.y) + c2;
    o.z = di.z * (ac.z + vv.z) + c2;
    o.w = di.w * (ac.w + vv.w) + c2;
    ((float4*)g_acc)[i] = make_float4(0.f, 0.f, 0.f, 0.f);
    ((float4*)out)[i] = o;
}

extern "C" void kernel_launch(void* const* d_in, const int* in_sizes, int n_in,
                              void* d_out, int out_size) {
    const float* x  = (const float*)d_in[0];
    const int*   ei = (const int*)d_in[1];    // [2, E] int32
    const float* ew = (const float*)d_in[2];
    const float* W1 = (const float*)d_in[3];
    const float* b1 = (const float*)d_in[4];
    const float* W2 = (const float*)d_in[5];
    const float* b2 = (const float*)d_in[6];
    const float* Wc = (const float*)d_in[7];
    const float* bc = (const float*)d_in[8];
    float* out = (float*)d_out;

    const int E = in_sizes[2];
    const int N = in_sizes[0] / IND;   // N % 4 == 0 (50000)
    const int* src = ei;
    const int* dst = ei + E;

    k_prep<<<1, 256>>>(W1, b1, W2, b2, Wc, bc);

    int tblocks  = (N * 32 + 255) / 256;          // warp-per-node
    int eblocks2 = (E / 2 + 1 + 255) / 256;       // 2 edges/thread (+tail slot)
    int n4 = N >> 2;
    int nblocks4 = (n4 + 255) / 256;

    k_t_deg<<<tblocks + eblocks2, 256>>>(x, dst, ew, N, E, tblocks);
    k_dinv<<<nblocks4, 256>>>(n4);
    k_prop<<<eblocks2, 256>>>(src, dst, ew, 0, E);
    k_mid<<<nblocks4, 256>>>(n4);
    k_prop<<<eblocks2, 256>>>(src, dst, ew, 1, E);
    k_final<<<nblocks4, 256>>>(out, n4);
}